// round 6
// baseline (speedup 1.0000x reference)
#include <cuda_runtime.h>
#include <cuda_bf16.h>
#include <cstdint>
#include <math.h>

#define N_SPK 512
#define N_UTT 64
#define D     1024
#define NM    (N_SPK * N_UTT)   // 32768
#define EPS   1e-6f

// ---------------- scratch (device globals; no runtime allocation) ----------
__device__ float          g_S[N_SPK * D];            // speaker sums (2 MiB)
__device__ __nv_bfloat16  g_cnorm[N_SPK * D];        // normalized centroids bf16 (1 MiB)
__device__ __nv_bfloat16  g_enorm[(size_t)NM * D];   // normalized utterances bf16 (64 MiB)
__device__ float          g_cos_self[NM];
__device__ float          g_prow[(size_t)NM * 2];    // per-row partial sum(exp) per N-slab
__device__ float          g_partial[128];

// ---------------- helpers ---------------------------------------------------
__device__ __forceinline__ uint32_t smem_u32(const void* p) {
    uint32_t a;
    asm("{ .reg .u64 t; cvta.to.shared.u64 t, %1; cvt.u32.u64 %0, t; }" : "=r"(a) : "l"(p));
    return a;
}
__device__ __forceinline__ void cp_async16(uint32_t saddr, const void* gsrc) {
    asm volatile("cp.async.cg.shared.global [%0], [%1], 16;" :: "r"(saddr), "l"(gsrc) : "memory");
}
__device__ __forceinline__ void cp_commit() {
    asm volatile("cp.async.commit_group;" ::: "memory");
}
template <int N>
__device__ __forceinline__ void cp_wait() {
    asm volatile("cp.async.wait_group %0;" :: "n"(N) : "memory");
}
__device__ __forceinline__ void ldsm_x4(uint32_t& r0, uint32_t& r1, uint32_t& r2, uint32_t& r3,
                                        uint32_t addr) {
    asm volatile("ldmatrix.sync.aligned.m8n8.x4.shared.b16 {%0,%1,%2,%3}, [%4];"
                 : "=r"(r0), "=r"(r1), "=r"(r2), "=r"(r3) : "r"(addr));
}

__device__ __forceinline__ float warpReduceSum(float v) {
    #pragma unroll
    for (int o = 16; o > 0; o >>= 1) v += __shfl_xor_sync(0xFFFFFFFFu, v, o);
    return v;
}
__device__ __forceinline__ float blockReduceSumBcast(float v, float* sred) {
    int lane = threadIdx.x & 31, w = threadIdx.x >> 5;
    int nw = blockDim.x >> 5;
    v = warpReduceSum(v);
    if (lane == 0) sred[w] = v;
    __syncthreads();
    if (threadIdx.x < 32) {
        float x = (threadIdx.x < nw) ? sred[threadIdx.x] : 0.0f;
        x = warpReduceSum(x);
        if (threadIdx.x == 0) sred[0] = x;
    }
    __syncthreads();
    float r = sred[0];
    __syncthreads();
    return r;
}

// ---------------- kernel 1: per-speaker sum + normalized centroid ----------
__global__ void __launch_bounds__(256) spk_kernel(const float* __restrict__ inp) {
    __shared__ float sred[32];
    const int n = blockIdx.x, t = threadIdx.x;
    const float4* base = reinterpret_cast<const float4*>(inp) + (size_t)n * N_UTT * (D / 4) + t;
    float4 s = make_float4(0.f, 0.f, 0.f, 0.f);
    #pragma unroll 8
    for (int m = 0; m < N_UTT; ++m) {
        float4 v = base[(size_t)m * (D / 4)];
        s.x += v.x; s.y += v.y; s.z += v.z; s.w += v.w;
    }
    reinterpret_cast<float4*>(g_S)[(size_t)n * (D / 4) + t] = s;
    const float invM = 1.0f / (float)N_UTT;
    float4 c = make_float4(s.x * invM, s.y * invM, s.z * invM, s.w * invM);
    float ss = c.x * c.x + c.y * c.y + c.z * c.z + c.w * c.w;
    ss = blockReduceSumBcast(ss, sred);
    float inv = 1.0f / sqrtf(fmaxf(ss, EPS));
    __nv_bfloat162 p0 = __floats2bfloat162_rn(c.x * inv, c.y * inv);
    __nv_bfloat162 p1 = __floats2bfloat162_rn(c.z * inv, c.w * inv);
    __nv_bfloat162* out = reinterpret_cast<__nv_bfloat162*>(g_cnorm) + (size_t)n * (D / 2) + 2 * t;
    out[0] = p0; out[1] = p1;
}

// ---------------- kernel 2: per-utterance normalize + cos_self -------------
__global__ void __launch_bounds__(256) utt_kernel(const float* __restrict__ inp) {
    __shared__ float sred[32];
    const int i = blockIdx.x, t = threadIdx.x;
    const int n = i >> 6;
    float4 x = reinterpret_cast<const float4*>(inp)[(size_t)i * (D / 4) + t];
    float4 S = reinterpret_cast<const float4*>(g_S)[(size_t)n * (D / 4) + t];
    const float invE = 1.0f / (float)(N_UTT - 1);
    float4 u = make_float4((S.x - x.x) * invE, (S.y - x.y) * invE,
                           (S.z - x.z) * invE, (S.w - x.w) * invE);
    float xx = x.x * x.x + x.y * x.y + x.z * x.z + x.w * x.w;
    float uu = u.x * u.x + u.y * u.y + u.z * u.z + u.w * u.w;
    float xu = x.x * u.x + x.y * u.y + x.z * u.z + x.w * u.w;
    xx = blockReduceSumBcast(xx, sred);
    uu = blockReduceSumBcast(uu, sred);
    xu = blockReduceSumBcast(xu, sred);
    float invx = 1.0f / sqrtf(fmaxf(xx, EPS));
    float invu = 1.0f / sqrtf(fmaxf(uu, EPS));
    if (t == 0) g_cos_self[i] = xu * invx * invu;
    __nv_bfloat162 p0 = __floats2bfloat162_rn(x.x * invx, x.y * invx);
    __nv_bfloat162 p1 = __floats2bfloat162_rn(x.z * invx, x.w * invx);
    __nv_bfloat162* out = reinterpret_cast<__nv_bfloat162*>(g_enorm) + (size_t)i * (D / 2) + 2 * t;
    out[0] = p0; out[1] = p1;
}

// ---------------- kernel 3: fused GEMM + sum(exp) epilogue -----------------
// Block tile 128x256, BK=32, 3-stage cp.async (dynamic smem), warp tile 64x64.
#define TILE_A_B 8192                        // 128 rows x 64B
#define TILE_B_B 16384                       // 256 rows x 64B
#define STAGE_B  (TILE_A_B + TILE_B_B)       // 24 KiB
#define GEMM_SMEM (3 * STAGE_B)              // 72 KiB
__device__ __forceinline__ uint32_t swz(int row, int chunk) {
    return (uint32_t)(row * 64 + ((chunk ^ ((row >> 1) & 3)) << 4));
}

__global__ void __launch_bounds__(256, 1) gemm_fused(const float* __restrict__ wp,
                                                     const float* __restrict__ bp) {
    extern __shared__ __align__(16) char smem_raw[];
    float* sred = reinterpret_cast<float*>(smem_raw);      // aliased in epilogue

    const int tid = threadIdx.x;
    const int bm = blockIdx.x, bn = blockIdx.y;
    const int warp = tid >> 5, lane = tid & 31;
    const int wm = warp & 1, wn = warp >> 1;     // 2 x 4 warp grid, warp tile 64x64
    const int g = lane >> 2, tg = lane & 3;
    const float W = *wp, Bb = *bp;
    const uint32_t sb = smem_u32(smem_raw);

    float acc[4][8][4];
    #pragma unroll
    for (int a = 0; a < 4; ++a)
        #pragma unroll
        for (int b = 0; b < 8; ++b)
            #pragma unroll
            for (int c = 0; c < 4; ++c) acc[a][b][c] = 0.f;

    // ---- cp.async staging: thread -> (row r0 + k*64, chunk s0) ----
    const int r0 = tid >> 2, s0 = tid & 3;
    const __nv_bfloat16* Ag = g_enorm + (size_t)(bm * 128 + r0) * D + s0 * 8;
    const __nv_bfloat16* Bg = g_cnorm + (size_t)(bn * 256 + r0) * D + s0 * 8;
    const uint32_t sw0 = swz(r0, s0), sw1 = swz(r0 + 64, s0);
    const uint32_t sw2 = swz(r0 + 128, s0), sw3 = swz(r0 + 192, s0);

    auto load_stage = [&](int stage, int kb) {
        const uint32_t ab = sb + stage * STAGE_B;
        const uint32_t bb = ab + TILE_A_B;
        cp_async16(ab + sw0, Ag + kb);
        cp_async16(ab + sw1, Ag + (size_t)64 * D + kb);
        cp_async16(bb + sw0, Bg + kb);
        cp_async16(bb + sw1, Bg + (size_t)64 * D + kb);
        cp_async16(bb + sw2, Bg + (size_t)128 * D + kb);
        cp_async16(bb + sw3, Bg + (size_t)192 * D + kb);
    };

    // ---- ldmatrix per-lane invariants ----
    const int a_row = wm * 64 + (lane & 15);                       // + mi*16
    const int a_ch  = lane >> 4;                                   // + kk/8
    const int b_row = wn * 64 + (lane & 7) + ((lane >> 4) << 3);   // + np*16
    const int b_ch  = (lane >> 3) & 1;                             // + kk/8

    // prologue: stages 0,1
    load_stage(0, 0);  cp_commit();
    load_stage(1, 32); cp_commit();

    const int NKT = D / 32;  // 32
    for (int kt = 0; kt < NKT; ++kt) {
        __syncthreads();                       // all warps done reading stage (kt-1)%3
        if (kt + 2 < NKT) load_stage((kt + 2) % 3, (kt + 2) * 32);
        cp_commit();                           // empty group when no loads -> uniform wait
        cp_wait<2>();                          // stage kt%3 resident
        __syncthreads();

        const uint32_t abase = sb + (kt % 3) * STAGE_B;
        const uint32_t bbase = abase + TILE_A_B;
        #pragma unroll
        for (int kk = 0; kk < 32; kk += 16) {
            const int kc = kk >> 3;
            uint32_t af[4][4];
            #pragma unroll
            for (int mi = 0; mi < 4; ++mi)
                ldsm_x4(af[mi][0], af[mi][1], af[mi][2], af[mi][3],
                        abase + swz(a_row + mi * 16, kc + a_ch));
            uint32_t bf_[8][2];
            #pragma unroll
            for (int np = 0; np < 4; ++np)   // each x4 covers ni = 2*np, 2*np+1
                ldsm_x4(bf_[2 * np][0], bf_[2 * np][1], bf_[2 * np + 1][0], bf_[2 * np + 1][1],
                        bbase + swz(b_row + np * 16, kc + b_ch));
            #pragma unroll
            for (int mi = 0; mi < 4; ++mi)
                #pragma unroll
                for (int ni = 0; ni < 8; ++ni) {
                    asm volatile(
                        "mma.sync.aligned.m16n8k16.row.col.f32.bf16.bf16.f32 "
                        "{%0,%1,%2,%3}, {%4,%5,%6,%7}, {%8,%9}, {%0,%1,%2,%3};\n"
                        : "+f"(acc[mi][ni][0]), "+f"(acc[mi][ni][1]),
                          "+f"(acc[mi][ni][2]), "+f"(acc[mi][ni][3])
                        : "r"(af[mi][0]), "r"(af[mi][1]), "r"(af[mi][2]), "r"(af[mi][3]),
                          "r"(bf_[ni][0]), "r"(bf_[ni][1]));
                }
        }
    }
    __syncthreads();   // done with tile smem; safe to alias as sred

    // ---- epilogue: per-row sum(exp(W*c + B)), diag column excluded ----
    const int dcol_local = 2 * bm + wm - bn * 256;
    #pragma unroll
    for (int mi = 0; mi < 4; ++mi) {
        #pragma unroll
        for (int half = 0; half < 2; ++half) {
            float ex = 0.0f;
            #pragma unroll
            for (int ni = 0; ni < 8; ++ni) {
                const int c0 = wn * 64 + ni * 8 + 2 * tg;
                const float v0 = acc[mi][ni][half * 2 + 0];
                const float v1 = acc[mi][ni][half * 2 + 1];
                ex += (c0     == dcol_local) ? 0.0f : __expf(fmaf(W, v0, Bb));
                ex += (c0 + 1 == dcol_local) ? 0.0f : __expf(fmaf(W, v1, Bb));
            }
            ex += __shfl_xor_sync(0xFFFFFFFFu, ex, 1);
            ex += __shfl_xor_sync(0xFFFFFFFFu, ex, 2);
            if (tg == 0) {
                const int row_local = wm * 64 + mi * 16 + half * 8 + g;
                sred[row_local * 4 + wn] = ex;
            }
        }
    }
    __syncthreads();
    if (tid < 128) {
        const float* p = sred + tid * 4;
        const float S = (p[0] + p[1]) + (p[2] + p[3]);
        g_prow[(size_t)(bm * 128 + tid) * 2 + bn] = S;
    }
}

// ---------------- kernel 4: merge partials -> per-row loss -> block sums ---
__global__ void __launch_bounds__(256) merge_kernel(const float* __restrict__ wp,
                                                    const float* __restrict__ bp) {
    __shared__ float sred[32];
    const int i = blockIdx.x * 256 + threadIdx.x;
    const float W = *wp, Bb = *bp;
    const float cs = g_cos_self[i];
    const float pos = fmaf(W, cs, Bb);
    const float2 p = *reinterpret_cast<const float2*>(g_prow + (size_t)i * 2);
    const float S = (p.x + p.y) + __expf(pos);
    float loss = __logf(S) - pos;
    loss = blockReduceSumBcast(loss, sred);
    if (threadIdx.x == 0) g_partial[blockIdx.x] = loss;
}

// ---------------- kernel 5: deterministic final reduction ------------------
__global__ void __launch_bounds__(128) final_reduce_kernel(float* __restrict__ out) {
    __shared__ float sred[4];
    const int t = threadIdx.x;
    float v = g_partial[t];
    v = warpReduceSum(v);
    if ((t & 31) == 0) sred[t >> 5] = v;
    __syncthreads();
    if (t == 0) out[0] = (sred[0] + sred[1]) + (sred[2] + sred[3]);
}

// ---------------- launch ----------------------------------------------------
extern "C" void kernel_launch(void* const* d_in, const int* in_sizes, int n_in,
                              void* d_out, int out_size) {
    const float* inp = (const float*)d_in[0];
    const float* w   = (const float*)d_in[1];
    const float* b   = (const float*)d_in[2];
    float* out = (float*)d_out;

    cudaFuncSetAttribute(gemm_fused, cudaFuncAttributeMaxDynamicSharedMemorySize, GEMM_SMEM);

    spk_kernel<<<N_SPK, 256>>>(inp);
    utt_kernel<<<NM, 256>>>(inp);
    dim3 gg(NM / 128, N_SPK / 256);
    gemm_fused<<<gg, 256, GEMM_SMEM>>>(w, b);
    merge_kernel<<<NM / 256, 256>>>(w, b);
    final_reduce_kernel<<<1, 128>>>(out);
}

// round 7
// speedup vs baseline: 1.1488x; 1.1488x over previous
#include <cuda_runtime.h>
#include <cuda_bf16.h>
#include <cstdint>
#include <math.h>

#define N_SPK 512
#define N_UTT 64
#define D     1024
#define NM    (N_SPK * N_UTT)   // 32768
#define EPS   1e-6f

// ---------------- scratch (device globals; no runtime allocation) ----------
__device__ float          g_S[N_SPK * D];            // speaker sums (2 MiB)
__device__ __nv_bfloat16  g_cnorm[N_SPK * D];        // normalized centroids bf16 (1 MiB)
__device__ __nv_bfloat16  g_enorm[(size_t)NM * D];   // normalized utterances bf16 (64 MiB)
__device__ float          g_cos_self[NM];
__device__ float          g_prow[(size_t)NM * 4];    // per-row partial sum(exp) per N-slab
__device__ float          g_partial[128];

// ---------------- helpers ---------------------------------------------------
__device__ __forceinline__ uint32_t smem_u32(const void* p) {
    uint32_t a;
    asm("{ .reg .u64 t; cvta.to.shared.u64 t, %1; cvt.u32.u64 %0, t; }" : "=r"(a) : "l"(p));
    return a;
}
__device__ __forceinline__ void cp_async16(uint32_t saddr, const void* gsrc) {
    asm volatile("cp.async.cg.shared.global [%0], [%1], 16;" :: "r"(saddr), "l"(gsrc) : "memory");
}
__device__ __forceinline__ void cp_commit() {
    asm volatile("cp.async.commit_group;" ::: "memory");
}
template <int N>
__device__ __forceinline__ void cp_wait() {
    asm volatile("cp.async.wait_group %0;" :: "n"(N) : "memory");
}
__device__ __forceinline__ void ldsm_x4(uint32_t& r0, uint32_t& r1, uint32_t& r2, uint32_t& r3,
                                        uint32_t addr) {
    asm volatile("ldmatrix.sync.aligned.m8n8.x4.shared.b16 {%0,%1,%2,%3}, [%4];"
                 : "=r"(r0), "=r"(r1), "=r"(r2), "=r"(r3) : "r"(addr));
}

__device__ __forceinline__ float warpReduceSum(float v) {
    #pragma unroll
    for (int o = 16; o > 0; o >>= 1) v += __shfl_xor_sync(0xFFFFFFFFu, v, o);
    return v;
}
__device__ __forceinline__ float blockReduceSumBcast(float v, float* sred) {
    int lane = threadIdx.x & 31, w = threadIdx.x >> 5;
    int nw = blockDim.x >> 5;
    v = warpReduceSum(v);
    if (lane == 0) sred[w] = v;
    __syncthreads();
    if (threadIdx.x < 32) {
        float x = (threadIdx.x < nw) ? sred[threadIdx.x] : 0.0f;
        x = warpReduceSum(x);
        if (threadIdx.x == 0) sred[0] = x;
    }
    __syncthreads();
    float r = sred[0];
    __syncthreads();
    return r;
}

// ---------------- kernel 1: per-speaker sum + normalized centroid ----------
__global__ void __launch_bounds__(256) spk_kernel(const float* __restrict__ inp) {
    __shared__ float sred[32];
    const int n = blockIdx.x, t = threadIdx.x;
    const float4* base = reinterpret_cast<const float4*>(inp) + (size_t)n * N_UTT * (D / 4) + t;
    float4 s = make_float4(0.f, 0.f, 0.f, 0.f);
    #pragma unroll 8
    for (int m = 0; m < N_UTT; ++m) {
        float4 v = base[(size_t)m * (D / 4)];
        s.x += v.x; s.y += v.y; s.z += v.z; s.w += v.w;
    }
    reinterpret_cast<float4*>(g_S)[(size_t)n * (D / 4) + t] = s;
    const float invM = 1.0f / (float)N_UTT;
    float4 c = make_float4(s.x * invM, s.y * invM, s.z * invM, s.w * invM);
    float ss = c.x * c.x + c.y * c.y + c.z * c.z + c.w * c.w;
    ss = blockReduceSumBcast(ss, sred);
    float inv = 1.0f / sqrtf(fmaxf(ss, EPS));
    __nv_bfloat162 p0 = __floats2bfloat162_rn(c.x * inv, c.y * inv);
    __nv_bfloat162 p1 = __floats2bfloat162_rn(c.z * inv, c.w * inv);
    __nv_bfloat162* out = reinterpret_cast<__nv_bfloat162*>(g_cnorm) + (size_t)n * (D / 2) + 2 * t;
    out[0] = p0; out[1] = p1;
}

// ---------------- kernel 2: per-utterance normalize + cos_self -------------
__global__ void __launch_bounds__(256) utt_kernel(const float* __restrict__ inp) {
    __shared__ float sred[32];
    const int i = blockIdx.x, t = threadIdx.x;
    const int n = i >> 6;
    float4 x = reinterpret_cast<const float4*>(inp)[(size_t)i * (D / 4) + t];
    float4 S = reinterpret_cast<const float4*>(g_S)[(size_t)n * (D / 4) + t];
    const float invE = 1.0f / (float)(N_UTT - 1);
    float4 u = make_float4((S.x - x.x) * invE, (S.y - x.y) * invE,
                           (S.z - x.z) * invE, (S.w - x.w) * invE);
    float xx = x.x * x.x + x.y * x.y + x.z * x.z + x.w * x.w;
    float uu = u.x * u.x + u.y * u.y + u.z * u.z + u.w * u.w;
    float xu = x.x * u.x + x.y * u.y + x.z * u.z + x.w * u.w;
    xx = blockReduceSumBcast(xx, sred);
    uu = blockReduceSumBcast(uu, sred);
    xu = blockReduceSumBcast(xu, sred);
    float invx = 1.0f / sqrtf(fmaxf(xx, EPS));
    float invu = 1.0f / sqrtf(fmaxf(uu, EPS));
    if (t == 0) g_cos_self[i] = xu * invx * invu;
    __nv_bfloat162 p0 = __floats2bfloat162_rn(x.x * invx, x.y * invx);
    __nv_bfloat162 p1 = __floats2bfloat162_rn(x.z * invx, x.w * invx);
    __nv_bfloat162* out = reinterpret_cast<__nv_bfloat162*>(g_enorm) + (size_t)i * (D / 2) + 2 * t;
    out[0] = p0; out[1] = p1;
}

// ---------------- kernel 3: fused GEMM + sum(exp) epilogue -----------------
// Block tile 128x128, BK=32, 3-stage cp.async, ldmatrix, 2 CTAs/SM.
#define TILE_B   8192                       // one 128x32 bf16 tile
#define STAGE_B  (2 * TILE_B)               // A + B
__device__ __forceinline__ uint32_t swz(int row, int chunk) {
    return (uint32_t)(row * 64 + ((chunk ^ ((row >> 1) & 3)) << 4));
}

__global__ void __launch_bounds__(256, 2) gemm_fused(const float* __restrict__ wp,
                                                     const float* __restrict__ bp) {
    __shared__ __align__(16) char smem_raw[3 * STAGE_B];   // 48 KiB
    float* sred = reinterpret_cast<float*>(smem_raw);      // aliased in epilogue

    const int tid = threadIdx.x;
    const int bm = blockIdx.x, bn = blockIdx.y;
    const int warp = tid >> 5, lane = tid & 31;
    const int wm = warp & 1, wn = warp >> 1;     // 2 x 4 warp grid, warp tile 64x32
    const int g = lane >> 2, tg = lane & 3;
    const float W = *wp, Bb = *bp;
    const uint32_t sb = smem_u32(smem_raw);

    float acc[4][4][4];
    #pragma unroll
    for (int a = 0; a < 4; ++a)
        #pragma unroll
        for (int b = 0; b < 4; ++b)
            #pragma unroll
            for (int c = 0; c < 4; ++c) acc[a][b][c] = 0.f;

    // ---- cp.async staging layout: thread -> (row r0/r0+64, chunk s0) ----
    const int r0 = tid >> 2, s0 = tid & 3;
    const __nv_bfloat16* Ag = g_enorm + (size_t)(bm * 128 + r0) * D + s0 * 8;
    const __nv_bfloat16* Bg = g_cnorm + (size_t)(bn * 128 + r0) * D + s0 * 8;
    const uint32_t sa_lo = swz(r0, s0), sa_hi = swz(r0 + 64, s0);

    auto load_stage = [&](int stage, int kb) {
        const uint32_t base = sb + stage * STAGE_B;
        cp_async16(base + sa_lo,          Ag + kb);
        cp_async16(base + sa_hi,          Ag + (size_t)64 * D + kb);
        cp_async16(base + TILE_B + sa_lo, Bg + kb);
        cp_async16(base + TILE_B + sa_hi, Bg + (size_t)64 * D + kb);
    };

    // ---- ldmatrix per-lane invariants ----
    const int a_row = wm * 64 + (lane & 15);             // + mi*16
    const int a_ch  = lane >> 4;                         // + kk/8
    const int b_row = wn * 32 + (lane & 7) + ((lane >> 4) << 3);   // + np*16
    const int b_ch  = (lane >> 3) & 1;                   // + kk/8

    // prologue: stages 0,1
    load_stage(0, 0);  cp_commit();
    load_stage(1, 32); cp_commit();

    const int NKT = D / 32;  // 32
    for (int kt = 0; kt < NKT; ++kt) {
        __syncthreads();                       // all warps done reading stage (kt-1)%3
        if (kt + 2 < NKT) load_stage((kt + 2) % 3, (kt + 2) * 32);
        cp_commit();                           // empty group when no loads -> uniform wait
        cp_wait<2>();                          // stage kt%3 resident
        __syncthreads();

        const uint32_t abase = sb + (kt % 3) * STAGE_B;
        const uint32_t bbase = abase + TILE_B;
        #pragma unroll
        for (int kk = 0; kk < 32; kk += 16) {
            const int kc = kk >> 3;
            uint32_t af[4][4];
            #pragma unroll
            for (int mi = 0; mi < 4; ++mi)
                ldsm_x4(af[mi][0], af[mi][1], af[mi][2], af[mi][3],
                        abase + swz(a_row + mi * 16, kc + a_ch));
            uint32_t bf_[4][2];
            #pragma unroll
            for (int np = 0; np < 2; ++np)   // each x4 covers ni = 2*np, 2*np+1
                ldsm_x4(bf_[2 * np][0], bf_[2 * np][1], bf_[2 * np + 1][0], bf_[2 * np + 1][1],
                        bbase + swz(b_row + np * 16, kc + b_ch));
            #pragma unroll
            for (int mi = 0; mi < 4; ++mi)
                #pragma unroll
                for (int ni = 0; ni < 4; ++ni) {
                    asm volatile(
                        "mma.sync.aligned.m16n8k16.row.col.f32.bf16.bf16.f32 "
                        "{%0,%1,%2,%3}, {%4,%5,%6,%7}, {%8,%9}, {%0,%1,%2,%3};\n"
                        : "+f"(acc[mi][ni][0]), "+f"(acc[mi][ni][1]),
                          "+f"(acc[mi][ni][2]), "+f"(acc[mi][ni][3])
                        : "r"(af[mi][0]), "r"(af[mi][1]), "r"(af[mi][2]), "r"(af[mi][3]),
                          "r"(bf_[ni][0]), "r"(bf_[ni][1]));
                }
        }
    }
    __syncthreads();   // done with tile smem; safe to alias as sred

    // ---- epilogue: per-row sum(exp(W*c + B)), diag column excluded ----
    const int dcol_local = 2 * bm + wm - bn * 128;
    #pragma unroll
    for (int mi = 0; mi < 4; ++mi) {
        #pragma unroll
        for (int half = 0; half < 2; ++half) {
            float ex = 0.0f;
            #pragma unroll
            for (int ni = 0; ni < 4; ++ni) {
                const int c0 = wn * 32 + ni * 8 + 2 * tg;
                const float v0 = acc[mi][ni][half * 2 + 0];
                const float v1 = acc[mi][ni][half * 2 + 1];
                ex += (c0     == dcol_local) ? 0.0f : __expf(fmaf(W, v0, Bb));
                ex += (c0 + 1 == dcol_local) ? 0.0f : __expf(fmaf(W, v1, Bb));
            }
            ex += __shfl_xor_sync(0xFFFFFFFFu, ex, 1);
            ex += __shfl_xor_sync(0xFFFFFFFFu, ex, 2);
            if (tg == 0) {
                const int row_local = wm * 64 + mi * 16 + half * 8 + g;
                sred[row_local * 4 + wn] = ex;
            }
        }
    }
    __syncthreads();
    if (tid < 128) {
        const float* p = sred + tid * 4;
        const float S = (p[0] + p[1]) + (p[2] + p[3]);
        g_prow[(size_t)(bm * 128 + tid) * 4 + bn] = S;
    }
}

// ---------------- kernel 4: merge partials -> per-row loss -> block sums ---
__global__ void __launch_bounds__(256) merge_kernel(const float* __restrict__ wp,
                                                    const float* __restrict__ bp) {
    __shared__ float sred[32];
    const int i = blockIdx.x * 256 + threadIdx.x;
    const float W = *wp, Bb = *bp;
    const float cs = g_cos_self[i];
    const float pos = fmaf(W, cs, Bb);
    const float4 p = *reinterpret_cast<const float4*>(g_prow + (size_t)i * 4);
    const float S = ((p.x + p.y) + (p.z + p.w)) + __expf(pos);
    float loss = __logf(S) - pos;
    loss = blockReduceSumBcast(loss, sred);
    if (threadIdx.x == 0) g_partial[blockIdx.x] = loss;
}

// ---------------- kernel 5: deterministic final reduction ------------------
__global__ void __launch_bounds__(128) final_reduce_kernel(float* __restrict__ out) {
    __shared__ float sred[4];
    const int t = threadIdx.x;
    float v = g_partial[t];
    v = warpReduceSum(v);
    if ((t & 31) == 0) sred[t >> 5] = v;
    __syncthreads();
    if (t == 0) out[0] = (sred[0] + sred[1]) + (sred[2] + sred[3]);
}

// ---------------- launch ----------------------------------------------------
extern "C" void kernel_launch(void* const* d_in, const int* in_sizes, int n_in,
                              void* d_out, int out_size) {
    const float* inp = (const float*)d_in[0];
    const float* w   = (const float*)d_in[1];
    const float* b   = (const float*)d_in[2];
    float* out = (float*)d_out;

    spk_kernel<<<N_SPK, 256>>>(inp);
    utt_kernel<<<NM, 256>>>(inp);
    dim3 gg(NM / 128, N_SPK / 128);
    gemm_fused<<<gg, 256>>>(w, b);
    merge_kernel<<<NM / 256, 256>>>(w, b);
    final_reduce_kernel<<<1, 128>>>(out);
}

// round 8
// speedup vs baseline: 1.2170x; 1.0594x over previous
#include <cuda_runtime.h>
#include <cuda_bf16.h>
#include <cstdint>
#include <math.h>

#define N_SPK 512
#define N_UTT 64
#define D     1024
#define NM    (N_SPK * N_UTT)   // 32768
#define EPS   1e-6f

// ---------------- scratch (device globals; no runtime allocation) ----------
__device__ __nv_bfloat16  g_cnorm[N_SPK * D];        // normalized centroids bf16 (1 MiB)
__device__ __nv_bfloat16  g_enorm[(size_t)NM * D];   // normalized utterances bf16 (64 MiB)
__device__ float          g_cos_self[NM];
__device__ float          g_prow[(size_t)NM * 4];    // per-row partial sum(exp) per N-slab
__device__ float          g_partial[128];

// ---------------- helpers ---------------------------------------------------
__device__ __forceinline__ uint32_t smem_u32(const void* p) {
    uint32_t a;
    asm("{ .reg .u64 t; cvta.to.shared.u64 t, %1; cvt.u32.u64 %0, t; }" : "=r"(a) : "l"(p));
    return a;
}
__device__ __forceinline__ void cp_async16(uint32_t saddr, const void* gsrc) {
    asm volatile("cp.async.cg.shared.global [%0], [%1], 16;" :: "r"(saddr), "l"(gsrc) : "memory");
}
__device__ __forceinline__ void cp_commit() {
    asm volatile("cp.async.commit_group;" ::: "memory");
}
template <int N>
__device__ __forceinline__ void cp_wait() {
    asm volatile("cp.async.wait_group %0;" :: "n"(N) : "memory");
}
__device__ __forceinline__ void ldsm_x4(uint32_t& r0, uint32_t& r1, uint32_t& r2, uint32_t& r3,
                                        uint32_t addr) {
    asm volatile("ldmatrix.sync.aligned.m8n8.x4.shared.b16 {%0,%1,%2,%3}, [%4];"
                 : "=r"(r0), "=r"(r1), "=r"(r2), "=r"(r3) : "r"(addr));
}

__device__ __forceinline__ float warpReduceSum(float v) {
    #pragma unroll
    for (int o = 16; o > 0; o >>= 1) v += __shfl_xor_sync(0xFFFFFFFFu, v, o);
    return v;
}
__device__ __forceinline__ float blockReduceSumBcast(float v, float* sred) {
    int lane = threadIdx.x & 31, w = threadIdx.x >> 5;
    int nw = blockDim.x >> 5;
    v = warpReduceSum(v);
    if (lane == 0) sred[w] = v;
    __syncthreads();
    if (threadIdx.x < 32) {
        float x = (threadIdx.x < nw) ? sred[threadIdx.x] : 0.0f;
        x = warpReduceSum(x);
        if (threadIdx.x == 0) sred[0] = x;
    }
    __syncthreads();
    float r = sred[0];
    __syncthreads();
    return r;
}

// ---------------- kernel 1: fused per-speaker centroid + utterance norm ----
// grid = 512 (one CTA per speaker), 256 threads. Thread t owns cols 4t..4t+3.
// Pass 1: speaker sum (regs) -> normalized centroid.
// Pass 2: per-utterance exclusion centroid, cos_self, normalized e (bf16).
__global__ void __launch_bounds__(256) pre_kernel(const float* __restrict__ inp) {
    __shared__ float sxx[32], suu[32], sxu[32], sred[32], sbc[2];
    const int n = blockIdx.x, t = threadIdx.x;
    const int lane = t & 31, w = t >> 5;
    const float4* base = reinterpret_cast<const float4*>(inp) + (size_t)n * N_UTT * (D / 4) + t;

    float4 s = make_float4(0.f, 0.f, 0.f, 0.f);
    #pragma unroll 8
    for (int m = 0; m < N_UTT; ++m) {
        float4 v = base[(size_t)m * (D / 4)];
        s.x += v.x; s.y += v.y; s.z += v.z; s.w += v.w;
    }
    const float invM = 1.0f / (float)N_UTT;
    float4 c = make_float4(s.x * invM, s.y * invM, s.z * invM, s.w * invM);
    float ss = c.x * c.x + c.y * c.y + c.z * c.z + c.w * c.w;
    ss = blockReduceSumBcast(ss, sred);
    {
        float inv = 1.0f / sqrtf(fmaxf(ss, EPS));
        __nv_bfloat162 p0 = __floats2bfloat162_rn(c.x * inv, c.y * inv);
        __nv_bfloat162 p1 = __floats2bfloat162_rn(c.z * inv, c.w * inv);
        __nv_bfloat162* out = reinterpret_cast<__nv_bfloat162*>(g_cnorm) + (size_t)n * (D / 2) + 2 * t;
        out[0] = p0; out[1] = p1;
    }

    // ---- pass 2 (L2-resident re-read), one-iteration prefetch ----
    const float invE = 1.0f / (float)(N_UTT - 1);
    float4 xn = base[0];
    for (int m = 0; m < N_UTT; ++m) {
        float4 x = xn;
        if (m + 1 < N_UTT) xn = base[(size_t)(m + 1) * (D / 4)];
        float4 u = make_float4((s.x - x.x) * invE, (s.y - x.y) * invE,
                               (s.z - x.z) * invE, (s.w - x.w) * invE);
        float xx = x.x * x.x + x.y * x.y + x.z * x.z + x.w * x.w;
        float uu = u.x * u.x + u.y * u.y + u.z * u.z + u.w * u.w;
        float xu = x.x * u.x + x.y * u.y + x.z * u.z + x.w * u.w;
        xx = warpReduceSum(xx); uu = warpReduceSum(uu); xu = warpReduceSum(xu);
        if (lane == 0) { sxx[w] = xx; suu[w] = uu; sxu[w] = xu; }
        __syncthreads();
        if (t == 0) {
            float a0 = 0.f, a1 = 0.f, a2 = 0.f;
            #pragma unroll
            for (int k = 0; k < 8; ++k) { a0 += sxx[k]; a1 += suu[k]; a2 += sxu[k]; }
            const float invx = 1.0f / sqrtf(fmaxf(a0, EPS));
            const float invu = 1.0f / sqrtf(fmaxf(a1, EPS));
            g_cos_self[n * N_UTT + m] = a2 * invx * invu;
            sbc[0] = invx;
        }
        __syncthreads();
        const float invx = sbc[0];
        __nv_bfloat162 p0 = __floats2bfloat162_rn(x.x * invx, x.y * invx);
        __nv_bfloat162 p1 = __floats2bfloat162_rn(x.z * invx, x.w * invx);
        __nv_bfloat162* out = reinterpret_cast<__nv_bfloat162*>(g_enorm)
                              + (size_t)(n * N_UTT + m) * (D / 2) + 2 * t;
        out[0] = p0; out[1] = p1;
        __syncthreads();   // protect sbc/sxx reuse next m
    }
}

// ---------------- kernel 2: fused GEMM + sum(exp) epilogue -----------------
// Block tile 128x128, BK=32, 3-stage cp.async, ldmatrix, 2 CTAs/SM.
// Single __syncthreads per mainloop iteration (loads issued after compute).
#define TILE_B   8192                       // one 128x32 bf16 tile
#define STAGE_B  (2 * TILE_B)               // A + B
__device__ __forceinline__ uint32_t swz(int row, int chunk) {
    return (uint32_t)(row * 64 + ((chunk ^ ((row >> 1) & 3)) << 4));
}

__global__ void __launch_bounds__(256, 2) gemm_fused(const float* __restrict__ wp,
                                                     const float* __restrict__ bp) {
    __shared__ __align__(16) char smem_raw[3 * STAGE_B];   // 48 KiB
    float* sred = reinterpret_cast<float*>(smem_raw);      // aliased in epilogue

    const int tid = threadIdx.x;
    const int bm = blockIdx.x, bn = blockIdx.y;
    const int warp = tid >> 5, lane = tid & 31;
    const int wm = warp & 1, wn = warp >> 1;     // 2 x 4 warp grid, warp tile 64x32
    const int g = lane >> 2, tg = lane & 3;
    const float W = *wp, Bb = *bp;
    const uint32_t sb = smem_u32(smem_raw);

    float acc[4][4][4];
    #pragma unroll
    for (int a = 0; a < 4; ++a)
        #pragma unroll
        for (int b = 0; b < 4; ++b)
            #pragma unroll
            for (int c = 0; c < 4; ++c) acc[a][b][c] = 0.f;

    const int r0 = tid >> 2, s0 = tid & 3;
    const __nv_bfloat16* Ag = g_enorm + (size_t)(bm * 128 + r0) * D + s0 * 8;
    const __nv_bfloat16* Bg = g_cnorm + (size_t)(bn * 128 + r0) * D + s0 * 8;
    const uint32_t sa_lo = swz(r0, s0), sa_hi = swz(r0 + 64, s0);

    auto load_stage = [&](int stage, int kb) {
        const uint32_t base = sb + stage * STAGE_B;
        cp_async16(base + sa_lo,          Ag + kb);
        cp_async16(base + sa_hi,          Ag + (size_t)64 * D + kb);
        cp_async16(base + TILE_B + sa_lo, Bg + kb);
        cp_async16(base + TILE_B + sa_hi, Bg + (size_t)64 * D + kb);
    };

    const int a_row = wm * 64 + (lane & 15);
    const int a_ch  = lane >> 4;
    const int b_row = wn * 32 + (lane & 7) + ((lane >> 4) << 3);
    const int b_ch  = (lane >> 3) & 1;

    // prologue: stages 0,1 in flight; stage 0 resident before loop
    load_stage(0, 0);  cp_commit();
    load_stage(1, 32); cp_commit();
    cp_wait<1>();
    __syncthreads();

    const int NKT = D / 32;  // 32
    for (int kt = 0; kt < NKT; ++kt) {
        // ---- compute on stage kt%3 (resident) ----
        const uint32_t abase = sb + (kt % 3) * STAGE_B;
        const uint32_t bbase = abase + TILE_B;
        #pragma unroll
        for (int kk = 0; kk < 32; kk += 16) {
            const int kc = kk >> 3;
            uint32_t af[4][4];
            #pragma unroll
            for (int mi = 0; mi < 4; ++mi)
                ldsm_x4(af[mi][0], af[mi][1], af[mi][2], af[mi][3],
                        abase + swz(a_row + mi * 16, kc + a_ch));
            uint32_t bf_[4][2];
            #pragma unroll
            for (int np = 0; np < 2; ++np)
                ldsm_x4(bf_[2 * np][0], bf_[2 * np][1], bf_[2 * np + 1][0], bf_[2 * np + 1][1],
                        bbase + swz(b_row + np * 16, kc + b_ch));
            #pragma unroll
            for (int mi = 0; mi < 4; ++mi)
                #pragma unroll
                for (int ni = 0; ni < 4; ++ni) {
                    asm volatile(
                        "mma.sync.aligned.m16n8k16.row.col.f32.bf16.bf16.f32 "
                        "{%0,%1,%2,%3}, {%4,%5,%6,%7}, {%8,%9}, {%0,%1,%2,%3};\n"
                        : "+f"(acc[mi][ni][0]), "+f"(acc[mi][ni][1]),
                          "+f"(acc[mi][ni][2]), "+f"(acc[mi][ni][3])
                        : "r"(af[mi][0]), "r"(af[mi][1]), "r"(af[mi][2]), "r"(af[mi][3]),
                          "r"(bf_[ni][0]), "r"(bf_[ni][1]));
                }
        }
        // ---- issue loads for stage kt+2 (writes stage (kt-1)%3: reads done) ----
        if (kt + 2 < NKT) load_stage((kt + 2) % 3, (kt + 2) * 32);
        cp_commit();          // empty group when no loads -> uniform wait depth
        cp_wait<1>();         // stage kt+1 resident
        __syncthreads();      // one barrier per iteration
    }

    // ---- epilogue: per-row sum(exp(W*c + B)), diag column excluded ----
    const int dcol_local = 2 * bm + wm - bn * 128;
    #pragma unroll
    for (int mi = 0; mi < 4; ++mi) {
        #pragma unroll
        for (int half = 0; half < 2; ++half) {
            float ex = 0.0f;
            #pragma unroll
            for (int ni = 0; ni < 4; ++ni) {
                const int c0 = wn * 32 + ni * 8 + 2 * tg;
                const float v0 = acc[mi][ni][half * 2 + 0];
                const float v1 = acc[mi][ni][half * 2 + 1];
                ex += (c0     == dcol_local) ? 0.0f : __expf(fmaf(W, v0, Bb));
                ex += (c0 + 1 == dcol_local) ? 0.0f : __expf(fmaf(W, v1, Bb));
            }
            ex += __shfl_xor_sync(0xFFFFFFFFu, ex, 1);
            ex += __shfl_xor_sync(0xFFFFFFFFu, ex, 2);
            if (tg == 0) {
                const int row_local = wm * 64 + mi * 16 + half * 8 + g;
                sred[row_local * 4 + wn] = ex;
            }
        }
    }
    __syncthreads();
    if (tid < 128) {
        const float* p = sred + tid * 4;
        const float S = (p[0] + p[1]) + (p[2] + p[3]);
        g_prow[(size_t)(bm * 128 + tid) * 4 + bn] = S;
    }
}

// ---------------- kernel 3: merge partials -> per-row loss -> block sums ---
__global__ void __launch_bounds__(256) merge_kernel(const float* __restrict__ wp,
                                                    const float* __restrict__ bp) {
    __shared__ float sred[32];
    const int i = blockIdx.x * 256 + threadIdx.x;
    const float W = *wp, Bb = *bp;
    const float cs = g_cos_self[i];
    const float pos = fmaf(W, cs, Bb);
    const float4 p = *reinterpret_cast<const float4*>(g_prow + (size_t)i * 4);
    const float S = ((p.x + p.y) + (p.z + p.w)) + __expf(pos);
    float loss = __logf(S) - pos;
    loss = blockReduceSumBcast(loss, sred);
    if (threadIdx.x == 0) g_partial[blockIdx.x] = loss;
}

// ---------------- kernel 4: deterministic final reduction ------------------
__global__ void __launch_bounds__(128) final_reduce_kernel(float* __restrict__ out) {
    __shared__ float sred[4];
    const int t = threadIdx.x;
    float v = g_partial[t];
    v = warpReduceSum(v);
    if ((t & 31) == 0) sred[t >> 5] = v;
    __syncthreads();
    if (t == 0) out[0] = (sred[0] + sred[1]) + (sred[2] + sred[3]);
}

// ---------------- launch ----------------------------------------------------
extern "C" void kernel_launch(void* const* d_in, const int* in_sizes, int n_in,
                              void* d_out, int out_size) {
    const float* inp = (const float*)d_in[0];
    const float* w   = (const float*)d_in[1];
    const float* b   = (const float*)d_in[2];
    float* out = (float*)d_out;

    pre_kernel<<<N_SPK, 256>>>(inp);
    dim3 gg(NM / 128, N_SPK / 128);
    gemm_fused<<<gg, 256>>>(w, b);
    merge_kernel<<<NM / 256, 256>>>(w, b);
    final_reduce_kernel<<<1, 128>>>(out);
}